// round 9
// baseline (speedup 1.0000x reference)
#include <cuda_runtime.h>
#include <math.h>
#include <stdint.h>

#define BATCH   2
#define SEQ     4096
#define DMODEL  512
#define NH      8
#define HD      64
#define NC      128
#define NS      64
#define TOPK    16
#define NROWS   (BATCH*SEQ)

// ---------------- scratch ----------------
__device__ float d_Q[NROWS*DMODEL];
__device__ float d_K[NROWS*DMODEL];
__device__ float d_V[NROWS*DMODEL];
__device__ float d_O[NROWS*DMODEL];
__device__ float d_KC[BATCH*NH*NC*HD];
__device__ float d_VC[BATCH*NH*NC*HD];
__device__ float d_G[NROWS*3];
__device__ int   d_SEL[BATCH*NH*NS*TOPK];

// ---------------- tf32 helpers ----------------
__device__ __forceinline__ float ftf(float x) {
    uint32_t u;
    asm("cvt.rna.tf32.f32 %0, %1;" : "=r"(u) : "f"(x));
    return __uint_as_float(u);
}
__device__ __forceinline__ float4 ftf4(float4 v) {
    return make_float4(ftf(v.x), ftf(v.y), ftf(v.z), ftf(v.w));
}
__device__ __forceinline__ void mma_tf32(float* c, const uint32_t* a, const uint32_t* b) {
    asm volatile(
        "mma.sync.aligned.m16n8k8.row.col.f32.tf32.tf32.f32 "
        "{%0,%1,%2,%3},{%4,%5,%6,%7},{%8,%9},{%0,%1,%2,%3};\n"
        : "+f"(c[0]), "+f"(c[1]), "+f"(c[2]), "+f"(c[3])
        : "r"(a[0]), "r"(a[1]), "r"(a[2]), "r"(a[3]), "r"(b[0]), "r"(b[1]));
}
__device__ __forceinline__ void split_tf32(float x, uint32_t& hi, uint32_t& lo) {
    float h = ftf(x);
    hi = __float_as_uint(h);
    lo = __float_as_uint(ftf(x - h));
}
#define U(x) __float_as_uint(x)

// ---------------- tf32 GEMM: 128x128 block tile, reg prefetch (unchanged) -
#define GPA 20
#define GPB 136
__global__ __launch_bounds__(256) void gemm512_tc(const float* __restrict__ Aext,
    const float* __restrict__ B0, const float* __restrict__ B1,
    const float* __restrict__ B2, float* __restrict__ Cext, int modeBase)
{
    int mode = modeBase + blockIdx.z;
    const float* A  = (mode == 3) ? d_O : Aext;
    const float* Bm = (mode == 1) ? B1 : (mode == 2) ? B2 : B0;
    float* C = (mode == 0) ? d_Q : (mode == 1) ? d_K : (mode == 2) ? d_V : Cext;

    __shared__ float As[128 * GPA];
    __shared__ float Bs[16 * GPB];

    int tid = threadIdx.x, lane = tid & 31, w = tid >> 5;
    int grp = lane >> 2, t4 = lane & 3;
    int wm = w & 3, wn = w >> 2;
    int m0 = blockIdx.y * 128, n0 = blockIdx.x * 128;

    int ar0 = tid >> 2,           ak0 = (tid & 3) * 4;
    int ar1 = (tid + 256) >> 2,   ak1 = ((tid + 256) & 3) * 4;
    int br0 = tid >> 5,           bc0 = (tid & 31) * 4;
    int br1 = (tid + 256) >> 5,   bc1 = ((tid + 256) & 31) * 4;

    float acc[2][8][4];
#pragma unroll
    for (int mt = 0; mt < 2; mt++)
#pragma unroll
        for (int nt = 0; nt < 8; nt++)
#pragma unroll
            for (int r = 0; r < 4; r++) acc[mt][nt][r] = 0.f;

    float4 apre0 = *(const float4*)(A + (size_t)(m0 + ar0) * 512 + ak0);
    float4 apre1 = *(const float4*)(A + (size_t)(m0 + ar1) * 512 + ak1);
    float4 bpre0 = *(const float4*)(Bm + (size_t)br0 * 512 + n0 + bc0);
    float4 bpre1 = *(const float4*)(Bm + (size_t)br1 * 512 + n0 + bc1);

    for (int k0 = 0; k0 < 512; k0 += 16) {
        *(float4*)(&As[ar0 * GPA + ak0]) = ftf4(apre0);
        *(float4*)(&As[ar1 * GPA + ak1]) = ftf4(apre1);
        *(float4*)(&Bs[br0 * GPB + bc0]) = ftf4(bpre0);
        *(float4*)(&Bs[br1 * GPB + bc1]) = ftf4(bpre1);
        __syncthreads();
        if (k0 + 16 < 512) {
            apre0 = *(const float4*)(A + (size_t)(m0 + ar0) * 512 + k0 + 16 + ak0);
            apre1 = *(const float4*)(A + (size_t)(m0 + ar1) * 512 + k0 + 16 + ak1);
            bpre0 = *(const float4*)(Bm + (size_t)(k0 + 16 + br0) * 512 + n0 + bc0);
            bpre1 = *(const float4*)(Bm + (size_t)(k0 + 16 + br1) * 512 + n0 + bc1);
        }
#pragma unroll
        for (int ks = 0; ks < 2; ks++) {
            int kb = ks * 8;
            uint32_t af[2][4], bf[8][2];
#pragma unroll
            for (int mt = 0; mt < 2; mt++) {
                int row = wm * 32 + mt * 16 + grp;
                af[mt][0] = U(As[row * GPA + kb + t4]);
                af[mt][1] = U(As[(row + 8) * GPA + kb + t4]);
                af[mt][2] = U(As[row * GPA + kb + t4 + 4]);
                af[mt][3] = U(As[(row + 8) * GPA + kb + t4 + 4]);
            }
#pragma unroll
            for (int nt = 0; nt < 8; nt++) {
                int col = wn * 64 + nt * 8 + grp;
                bf[nt][0] = U(Bs[(kb + t4) * GPB + col]);
                bf[nt][1] = U(Bs[(kb + t4 + 4) * GPB + col]);
            }
#pragma unroll
            for (int mt = 0; mt < 2; mt++)
#pragma unroll
                for (int nt = 0; nt < 8; nt++)
                    mma_tf32(acc[mt][nt], af[mt], bf[nt]);
        }
        __syncthreads();
    }
#pragma unroll
    for (int mt = 0; mt < 2; mt++)
#pragma unroll
        for (int nt = 0; nt < 8; nt++) {
            int row = m0 + wm * 32 + mt * 16 + grp;
            int col = n0 + wn * 64 + nt * 8 + 2 * t4;
            *(float2*)(C + (size_t)row * 512 + col) =
                make_float2(acc[mt][nt][0], acc[mt][nt][1]);
            *(float2*)(C + (size_t)(row + 8) * 512 + col) =
                make_float2(acc[mt][nt][2], acc[mt][nt][3]);
        }
}

// ---------------- gate (unchanged) ----------------
__global__ __launch_bounds__(256) void gate_kernel(const float* __restrict__ x,
                                                   const float* __restrict__ Wg)
{
    int w = threadIdx.x >> 5, lane = threadIdx.x & 31;
    int row = blockIdx.x * 8 + w;
    float p0 = 0, p1 = 0, p2 = 0;
#pragma unroll
    for (int c = 0; c < 4; c++) {
        int d = c * 128 + lane * 4;
        float4 xv = *(const float4*)(x + (size_t)row * 512 + d);
        p0 += xv.x * Wg[d * 3]     + xv.y * Wg[d * 3 + 3] +
              xv.z * Wg[d * 3 + 6] + xv.w * Wg[d * 3 + 9];
        p1 += xv.x * Wg[d * 3 + 1] + xv.y * Wg[d * 3 + 4] +
              xv.z * Wg[d * 3 + 7] + xv.w * Wg[d * 3 + 10];
        p2 += xv.x * Wg[d * 3 + 2] + xv.y * Wg[d * 3 + 5] +
              xv.z * Wg[d * 3 + 8] + xv.w * Wg[d * 3 + 11];
    }
#pragma unroll
    for (int o = 16; o; o >>= 1) {
        p0 += __shfl_xor_sync(0xffffffffu, p0, o);
        p1 += __shfl_xor_sync(0xffffffffu, p1, o);
        p2 += __shfl_xor_sync(0xffffffffu, p2, o);
    }
    if (lane == 0) {
        d_G[row * 3 + 0] = 1.f / (1.f + expf(-p0));
        d_G[row * 3 + 1] = 1.f / (1.f + expf(-p1));
        d_G[row * 3 + 2] = 1.f / (1.f + expf(-p2));
    }
}

// ---------------- compressed K/V means (unchanged) ----------------
__global__ __launch_bounds__(256) void compress_kernel()
{
    int idx = blockIdx.x * 256 + threadIdx.x;
    int d = idx & 63, n = (idx >> 6) & 127, h = (idx >> 13) & 7, b = idx >> 16;
    const float* kp = d_K + (size_t)(b * SEQ + n * 32) * 512 + h * 64 + d;
    const float* vp = d_V + (size_t)(b * SEQ + n * 32) * 512 + h * 64 + d;
    float ks = 0, vs = 0;
#pragma unroll
    for (int r = 0; r < 32; r++) { ks += kp[r * 512]; vs += vp[r * 512]; }
    d_KC[idx] = ks * (1.f / 32.f);
    d_VC[idx] = vs * (1.f / 32.f);
}

// ---------------- compressed attention + top-k (unchanged) ----------------
#define CQ 68
#define CK 72
#define CS 132
__global__ __launch_bounds__(256) void cmp_attn_mma()
{
    extern __shared__ float sm[];
    float* qs   = sm;
    float* kv   = qs + 64 * CQ;
    float* ps   = kv + 128 * CK;
    float* redm = ps + 64 * CS;
    float* reds = redm + 256;
    float* impb = reds + 256;

    int g = blockIdx.x, h = blockIdx.y, b = blockIdx.z;
    int tid = threadIdx.x, lane = tid & 31, w = tid >> 5;
    int grp = lane >> 2, t4 = lane & 3;
    int wm = w & 1, wn = w >> 1;
    int qbase = g * 64;

    for (int i = tid; i < 1024; i += 256) {
        int r = i >> 4, d4 = (i & 15) * 4;
        float4 v = *(const float4*)(d_Q + (size_t)(b * SEQ + qbase + r) * 512 + h * 64 + d4);
        *(float4*)(&qs[r * CQ + d4]) = v;
    }
    int cbase = ((b * NH + h) * NC) * HD;
    for (int i = tid; i < 2048; i += 256) {
        int r = i >> 4, d4 = (i & 15) * 4;
        float4 v = *(const float4*)(d_KC + cbase + r * 64 + d4);
        *(float4*)(&kv[r * CK + d4]) = v;
    }
    __syncthreads();

    float s[2][4][4];
#pragma unroll
    for (int mt = 0; mt < 2; mt++)
#pragma unroll
        for (int nt = 0; nt < 4; nt++)
#pragma unroll
            for (int r = 0; r < 4; r++) s[mt][nt][r] = 0.f;
#pragma unroll
    for (int ks = 0; ks < 8; ks++) {
        int kk = ks * 8;
        uint32_t ah[2][4], al[2][4], bh[4][2], bl[4][2];
#pragma unroll
        for (int mt = 0; mt < 2; mt++) {
            int row = wm * 32 + mt * 16 + grp;
            split_tf32(qs[row * CQ + kk + t4],           ah[mt][0], al[mt][0]);
            split_tf32(qs[(row + 8) * CQ + kk + t4],     ah[mt][1], al[mt][1]);
            split_tf32(qs[row * CQ + kk + t4 + 4],       ah[mt][2], al[mt][2]);
            split_tf32(qs[(row + 8) * CQ + kk + t4 + 4], ah[mt][3], al[mt][3]);
        }
#pragma unroll
        for (int nt = 0; nt < 4; nt++) {
            int key = wn * 32 + nt * 8 + grp;
            split_tf32(kv[key * CK + kk + t4],     bh[nt][0], bl[nt][0]);
            split_tf32(kv[key * CK + kk + t4 + 4], bh[nt][1], bl[nt][1]);
        }
#pragma unroll
        for (int mt = 0; mt < 2; mt++)
#pragma unroll
            for (int nt = 0; nt < 4; nt++) {
                mma_tf32(s[mt][nt], ah[mt], bl[nt]);
                mma_tf32(s[mt][nt], al[mt], bh[nt]);
                mma_tf32(s[mt][nt], ah[mt], bh[nt]);
            }
    }

    int nval[2][2];
#pragma unroll
    for (int mt = 0; mt < 2; mt++)
#pragma unroll
        for (int hf = 0; hf < 2; hf++) {
            int pos = qbase + wm * 32 + mt * 16 + grp + hf * 8;
            nval[mt][hf] = (pos >= 31) ? ((pos - 31) >> 5) + 1 : 0;
        }
#pragma unroll
    for (int mt = 0; mt < 2; mt++)
#pragma unroll
        for (int nt = 0; nt < 4; nt++)
#pragma unroll
            for (int r = 0; r < 4; r++) {
                int c = wn * 32 + nt * 8 + 2 * t4 + (r & 1);
                bool valid = c < nval[mt][r >> 1];
                s[mt][nt][r] = valid ? s[mt][nt][r] * 0.125f : -1e30f;
            }

#pragma unroll
    for (int mt = 0; mt < 2; mt++)
#pragma unroll
        for (int hf = 0; hf < 2; hf++) {
            float rm = -1e30f;
#pragma unroll
            for (int nt = 0; nt < 4; nt++)
                rm = fmaxf(rm, fmaxf(s[mt][nt][2 * hf], s[mt][nt][2 * hf + 1]));
            rm = fmaxf(rm, __shfl_xor_sync(0xffffffffu, rm, 1));
            rm = fmaxf(rm, __shfl_xor_sync(0xffffffffu, rm, 2));
            if (t4 == 0)
                redm[(wm * 32 + mt * 16 + grp + hf * 8) * 4 + wn] = rm;
        }
    __syncthreads();

    for (int i = tid; i < 2048; i += 256) {
        int r = i >> 4, d4 = (i & 15) * 4;
        float4 v = *(const float4*)(d_VC + cbase + r * 64 + d4);
        *(float4*)(&kv[r * CK + d4]) = v;
    }
#pragma unroll
    for (int mt = 0; mt < 2; mt++)
#pragma unroll
        for (int hf = 0; hf < 2; hf++) {
            int row = wm * 32 + mt * 16 + grp + hf * 8;
            float4 rmv = *(float4*)(&redm[row * 4]);
            float gmax = fmaxf(fmaxf(rmv.x, rmv.y), fmaxf(rmv.z, rmv.w));
            float rs = 0.f;
#pragma unroll
            for (int nt = 0; nt < 4; nt++) {
                float e0 = __expf(s[mt][nt][2 * hf]     - gmax);
                float e1 = __expf(s[mt][nt][2 * hf + 1] - gmax);
                s[mt][nt][2 * hf] = e0;
                s[mt][nt][2 * hf + 1] = e1;
                rs += e0 + e1;
            }
            rs += __shfl_xor_sync(0xffffffffu, rs, 1);
            rs += __shfl_xor_sync(0xffffffffu, rs, 2);
            if (t4 == 0) reds[row * 4 + wn] = rs;
        }
    __syncthreads();

#pragma unroll
    for (int mt = 0; mt < 2; mt++)
#pragma unroll
        for (int hf = 0; hf < 2; hf++) {
            int row = wm * 32 + mt * 16 + grp + hf * 8;
            float4 rsv = *(float4*)(&reds[row * 4]);
            float tot = rsv.x + rsv.y + rsv.z + rsv.w;
            float inv = (nval[mt][hf] > 0) ? 1.f / tot : 0.f;
#pragma unroll
            for (int nt = 0; nt < 4; nt++) {
                int col = wn * 32 + nt * 8 + 2 * t4;
                ps[row * CS + col]     = s[mt][nt][2 * hf]     * inv;
                ps[row * CS + col + 1] = s[mt][nt][2 * hf + 1] * inv;
            }
        }
    __syncthreads();

    float o[2][2][4];
#pragma unroll
    for (int mt = 0; mt < 2; mt++)
#pragma unroll
        for (int nt = 0; nt < 2; nt++)
#pragma unroll
            for (int r = 0; r < 4; r++) o[mt][nt][r] = 0.f;
#pragma unroll
    for (int ks = 0; ks < 16; ks++) {
        int kk = ks * 8;
        uint32_t af[2][4], bf[2][2];
#pragma unroll
        for (int mt = 0; mt < 2; mt++) {
            int row = wm * 32 + mt * 16 + grp;
            af[mt][0] = U(ftf(ps[row * CS + kk + t4]));
            af[mt][1] = U(ftf(ps[(row + 8) * CS + kk + t4]));
            af[mt][2] = U(ftf(ps[row * CS + kk + t4 + 4]));
            af[mt][3] = U(ftf(ps[(row + 8) * CS + kk + t4 + 4]));
        }
#pragma unroll
        for (int nt = 0; nt < 2; nt++) {
            int dcol = wn * 16 + nt * 8 + grp;
            bf[nt][0] = U(ftf(kv[(kk + t4) * CK + dcol]));
            bf[nt][1] = U(ftf(kv[(kk + t4 + 4) * CK + dcol]));
        }
#pragma unroll
        for (int mt = 0; mt < 2; mt++)
#pragma unroll
            for (int nt = 0; nt < 2; nt++)
                mma_tf32(o[mt][nt], af[mt], bf[nt]);
    }

#pragma unroll
    for (int mt = 0; mt < 2; mt++)
#pragma unroll
        for (int hf = 0; hf < 2; hf++) {
            int qp = qbase + wm * 32 + mt * 16 + grp + hf * 8;
            float g0 = d_G[(b * SEQ + qp) * 3 + 0];
#pragma unroll
            for (int nt = 0; nt < 2; nt++) {
                int dcol = wn * 16 + nt * 8 + 2 * t4;
                size_t ob = (size_t)(b * SEQ + qp) * 512 + h * 64 + dcol;
                *(float2*)(d_O + ob) = make_float2(o[mt][nt][2 * hf] * g0,
                                                   o[mt][nt][2 * hf + 1] * g0);
            }
        }
    __syncthreads();

    if (tid < 64) {
        float v = 0.f;
        for (int q = 0; q < 64; q++)
            v += ps[q * CS + 2 * tid] + ps[q * CS + 2 * tid + 1];
        impb[tid] = v;
    }
    __syncthreads();
    if (w == 0) {
        int j0 = lane, j1 = lane + 32;
        float v0 = (j0 <= g) ? impb[j0] + (j0 == g ? 1e9f : 0.f) : -1e30f;
        float v1 = (j1 <= g) ? impb[j1] + (j1 == g ? 1e9f : 0.f) : -1e30f;
        int selbase = ((b * NH + h) * NS + g) * TOPK;
        for (int r = 0; r < TOPK; r++) {
            float bv; int bi;
            if (v0 >= v1) { bv = v0; bi = j0; } else { bv = v1; bi = j1; }
#pragma unroll
            for (int o2 = 16; o2; o2 >>= 1) {
                float ov = __shfl_xor_sync(0xffffffffu, bv, o2);
                int   oi = __shfl_xor_sync(0xffffffffu, bi, o2);
                if (ov > bv || (ov == bv && oi < bi)) { bv = ov; bi = oi; }
            }
            if (lane == 0) d_SEL[selbase + r] = bi;
            if (bi == j0) v0 = -3e30f;
            if (bi == j1) v1 = -3e30f;
        }
    }
}

// ---------------- fused sel+win: producer/consumer warp specialization -----
// warps 0-3 = consumers, each owns 16 full score rows (warp-local softmax).
// warps 4-7 = producers: stream K/V tile t+1 into double-buffered smem.
// Exactly one __syncthreads per tile.
#define QP 72
#define KP 68
#define VP 72
#define PP 72
#define KS_SZ (64*KP)
#define VS_SZ (64*VP)

__device__ __forceinline__ void fill_tile(float* Ks, float* Vs, int ptid,
                                          size_t kbase)
{
#pragma unroll
    for (int i = 0; i < 8; i++) {
        int idx = ptid + i * 128;
        int r = idx >> 4, d4 = (idx & 15) * 4;
        float4 k4 = *(const float4*)(d_K + kbase + (size_t)r * 512 + d4);
        float4 v4 = *(const float4*)(d_V + kbase + (size_t)r * 512 + d4);
        *(float4*)(&Ks[r * KP + d4]) = ftf4(k4);
        *(float4*)(&Vs[r * VP + d4]) = ftf4(v4);
    }
}

__global__ void __launch_bounds__(256, 2) selwin_fused()
{
    extern __shared__ float sm[];
    float* qs  = sm;                    // 64*72 paired
    float* Ksb = qs + 64 * QP;          // 2 * 64*68
    float* Vsb = Ksb + 2 * KS_SZ;       // 2 * 64*72
    float* ps  = Vsb + 2 * VS_SZ;       // 64*72 paired, consumer-warp-private rows

    int g = blockIdx.x, hh = blockIdx.y, b = blockIdx.z;
    int tid = threadIdx.x, lane = tid & 31, wid = tid >> 5;
    int grp = lane >> 2, t4 = lane & 3;
    int qbase = g * 64;
    bool consumer = (wid < 4);
    int wq = wid;             // consumer q-row group
    int ptid = tid - 128;     // producer lane id

    // tile list (all threads compute; cheap)
    int selbase = ((b * NH + hh) * NS + g) * TOPK;
    int kblist[25];
    int nsel = 0;
#pragma unroll
    for (int it = 0; it < TOPK; it++) {
        int kb = d_SEL[selbase + it];
        if (kb <= g) kblist[nsel++] = kb;
    }
    int ntot = nsel;
    {
        int st = (g > 8) ? g - 8 : 0;
        for (int kb = st; kb <= g; kb++) kblist[ntot++] = kb;
    }

    if (consumer) {
        // consumers load Q (paired tf32 layout): 4 slots each
#pragma unroll
        for (int ii = 0; ii < 4; ii++) {
            int i = tid + ii * 128;
            int r = i >> 3, g8 = (i & 7) * 8;
            const float* src = d_Q + (size_t)(b * SEQ + qbase + r) * 512 + hh * 64 + g8;
            float4 lo = *(const float4*)src;
            float4 hi = *(const float4*)(src + 4);
            float2* dst = (float2*)(&qs[r * QP + g8]);
            dst[0] = make_float2(ftf(lo.x), ftf(hi.x));
            dst[1] = make_float2(ftf(lo.y), ftf(hi.y));
            dst[2] = make_float2(ftf(lo.z), ftf(hi.z));
            dst[3] = make_float2(ftf(lo.w), ftf(hi.w));
        }
    } else {
        // producers fill buffer 0 with tile 0
        size_t kbase0 = (size_t)(b * SEQ + kblist[0] * 64) * 512 + hh * 64;
        fill_tile(Ksb, Vsb, ptid, kbase0);
    }
    __syncthreads();

    if (consumer) {
        // row state: hf=0 -> row wq*16+grp, hf=1 -> +8
        float o[8][4];
#pragma unroll
        for (int nt = 0; nt < 8; nt++)
#pragma unroll
            for (int r = 0; r < 4; r++) o[nt][r] = 0.f;
        float m[2] = {-1e30f, -1e30f}, l[2] = {0.f, 0.f};
        float gv1[2], gv2[2];
#pragma unroll
        for (int hf = 0; hf < 2; hf++) {
            int qp = qbase + wq * 16 + grp + hf * 8;
            gv1[hf] = d_G[(b * SEQ + qp) * 3 + 1];
            gv2[hf] = d_G[(b * SEQ + qp) * 3 + 2];
        }
        int posA = ((t4 & 1) << 2) + (t4 >> 1);
        int rowA = wq * 16 + grp;

        for (int t = 0; t < ntot; t++) {
            if (t == nsel) {
                // finalize sel phase directly into d_O, reset state
#pragma unroll
                for (int hf = 0; hf < 2; hf++) {
                    int qp = qbase + rowA + hf * 8;
                    float inv = gv1[hf] / l[hf];
#pragma unroll
                    for (int nt = 0; nt < 8; nt++) {
                        size_t ob = (size_t)(b * SEQ + qp) * 512 + hh * 64 + nt * 8 + 2 * t4;
                        float2 cur = *(float2*)(d_O + ob);
                        cur.x += o[nt][2 * hf]     * inv;
                        cur.y += o[nt][2 * hf + 1] * inv;
                        *(float2*)(d_O + ob) = cur;
                        o[nt][2 * hf] = 0.f; o[nt][2 * hf + 1] = 0.f;
                    }
                    m[hf] = -1e30f; l[hf] = 0.f;
                }
            }
            int kb = kblist[t];
            bool winph = (t >= nsel);
            float* Ks = Ksb + (t & 1) * KS_SZ;
            float* Vs = Vsb + (t & 1) * VS_SZ;

            // ---- QK^T: warp tile 16q x 64k ----
            float s[8][4];
#pragma unroll
            for (int nt = 0; nt < 8; nt++)
#pragma unroll
                for (int r = 0; r < 4; r++) s[nt][r] = 0.f;
#pragma unroll
            for (int ks = 0; ks < 8; ks++) {
                int kk = ks * 8;
                uint32_t af[4];
                float2 a0 = *(float2*)(&qs[rowA * QP + kk + 2 * t4]);
                float2 a1 = *(float2*)(&qs[(rowA + 8) * QP + kk + 2 * t4]);
                af[0] = U(a0.x); af[2] = U(a0.y);
                af[1] = U(a1.x); af[3] = U(a1.y);
#pragma unroll
                for (int nt = 0; nt < 8; nt++) {
                    int key = nt * 8 + grp;
                    uint32_t bf[2];
                    bf[0] = U(Ks[key * KP + kk + t4]);
                    bf[1] = U(Ks[key * KP + kk + t4 + 4]);
                    mma_tf32(s[nt], af, bf);
                }
            }

            // mask + scale
#pragma unroll
            for (int nt = 0; nt < 8; nt++)
#pragma unroll
                for (int r = 0; r < 4; r++) {
                    int qp = qbase + rowA + (r >> 1) * 8;
                    int kp = kb * 64 + nt * 8 + 2 * t4 + (r & 1);
                    bool valid = (kp <= qp) && (!winph || (kp + 512 > qp));
                    s[nt][r] = valid ? s[nt][r] * 0.125f : -1e30f;
                }

            // warp-local softmax (rows fully owned: reduce over quad only)
#pragma unroll
            for (int hf = 0; hf < 2; hf++) {
                float rm = -1e30f;
#pragma unroll
                for (int nt = 0; nt < 8; nt++)
                    rm = fmaxf(rm, fmaxf(s[nt][2 * hf], s[nt][2 * hf + 1]));
                rm = fmaxf(rm, __shfl_xor_sync(0xffffffffu, rm, 1));
                rm = fmaxf(rm, __shfl_xor_sync(0xffffffffu, rm, 2));
                float mn = fmaxf(m[hf], rm);
                float cr = __expf(m[hf] - mn);
                float rs = 0.f;
#pragma unroll
                for (int nt = 0; nt < 8; nt++) {
                    float p0 = __expf(s[nt][2 * hf]     - mn);
                    float p1 = __expf(s[nt][2 * hf + 1] - mn);
                    rs += p0 + p1;
                    int gb = nt * 8;
                    int rowl = rowA + hf * 8;
                    ps[rowl * PP + gb + posA]     = ftf(p0);
                    ps[rowl * PP + gb + posA + 2] = ftf(p1);
                }
                rs += __shfl_xor_sync(0xffffffffu, rs, 1);
                rs += __shfl_xor_sync(0xffffffffu, rs, 2);
                l[hf] = l[hf] * cr + rs;
                m[hf] = mn;
#pragma unroll
                for (int nt = 0; nt < 8; nt++) {
                    o[nt][2 * hf]     *= cr;
                    o[nt][2 * hf + 1] *= cr;
                }
            }
            __syncwarp();

            // ---- P*V: warp tile 16q x 64d ----
#pragma unroll
            for (int ks = 0; ks < 8; ks++) {
                int kk = ks * 8;
                uint32_t af[4];
                float2 p0 = *(float2*)(&ps[rowA * PP + kk + 2 * t4]);
                float2 p1 = *(float2*)(&ps[(rowA + 8) * PP + kk + 2 * t4]);
                af[0] = U(p0.x); af[2] = U(p0.y);
                af[1] = U(p1.x); af[3] = U(p1.y);
#pragma unroll
                for (int nt = 0; nt < 8; nt++) {
                    int dcol = nt * 8 + grp;
                    uint32_t bf[2];
                    bf[0] = U(Vs[(kk + t4) * VP + dcol]);
                    bf[1] = U(Vs[(kk + t4 + 4) * VP + dcol]);
                    mma_tf32(o[nt], af, bf);
                }
            }
            __syncwarp();
            __syncthreads();   // tile done; producer's t+1 buffer visible
        }

        // finalize window phase
#pragma unroll
        for (int hf = 0; hf < 2; hf++) {
            int qp = qbase + rowA + hf * 8;
            float inv = gv2[hf] / l[hf];
#pragma unroll
            for (int nt = 0; nt < 8; nt++) {
                size_t ob = (size_t)(b * SEQ + qp) * 512 + hh * 64 + nt * 8 + 2 * t4;
                float2 cur = *(float2*)(d_O + ob);
                cur.x += o[nt][2 * hf]     * inv;
                cur.y += o[nt][2 * hf + 1] * inv;
                *(float2*)(d_O + ob) = cur;
            }
        }
    } else {
        // producer loop: fill buffer (t+1)&1 with tile t+1
        for (int t = 0; t < ntot; t++) {
            if (t + 1 < ntot) {
                int nxt = (t + 1) & 1;
                size_t kbase = (size_t)(b * SEQ + kblist[t + 1] * 64) * 512 + hh * 64;
                fill_tile(Ksb + nxt * KS_SZ, Vsb + nxt * VS_SZ, ptid, kbase);
            }
            __syncthreads();
        }
    }
}

// ---------------------------------------------------------------------------
extern "C" void kernel_launch(void* const* d_in, const int* in_sizes, int n_in,
                              void* d_out, int out_size)
{
    const float* x  = (const float*)d_in[0];
    const float* Wq = (const float*)d_in[1];
    const float* Wk = (const float*)d_in[2];
    const float* Wv = (const float*)d_in[3];
    const float* Wo = (const float*)d_in[4];
    const float* Wg = (const float*)d_in[5];
    float* y = (float*)d_out;

    // selwin smem: 64*(72 + 2*68 + 2*72 + 72) floats = 108544 bytes
    cudaFuncSetAttribute(cmp_attn_mma,
                         cudaFuncAttributeMaxDynamicSharedMemorySize, 90368);
    cudaFuncSetAttribute(selwin_fused,
                         cudaFuncAttributeMaxDynamicSharedMemorySize, 108544);

    gemm512_tc<<<dim3(4, 64, 3), 256>>>(x, Wq, Wk, Wv, nullptr, 0);
    gate_kernel<<<NROWS / 8, 256>>>(x, Wg);
    compress_kernel<<<(BATCH * NH * NC * HD) / 256, 256>>>();
    cmp_attn_mma<<<dim3(64, 8, 2), 256, 90368>>>();
    selwin_fused<<<dim3(64, 8, 2), 256, 108544>>>();
    gemm512_tc<<<dim3(4, 64, 1), 256>>>(nullptr, Wo, nullptr, nullptr, y, 3);
}

// round 10
// speedup vs baseline: 1.0195x; 1.0195x over previous
#include <cuda_runtime.h>
#include <math.h>
#include <stdint.h>

#define BATCH   2
#define SEQ     4096
#define DMODEL  512
#define NH      8
#define HD      64
#define NC      128
#define NS      64
#define TOPK    16
#define NROWS   (BATCH*SEQ)

// ---------------- scratch ----------------
__device__ float d_Q[NROWS*DMODEL];
__device__ float d_K[NROWS*DMODEL];
__device__ float d_V[NROWS*DMODEL];
__device__ float d_O[NROWS*DMODEL];
__device__ float d_KC[BATCH*NH*NC*HD];
__device__ float d_VC[BATCH*NH*NC*HD];
__device__ float d_G[NROWS*3];
__device__ int   d_SEL[BATCH*NH*NS*TOPK];

// ---------------- tf32 helpers ----------------
__device__ __forceinline__ float ftf(float x) {
    uint32_t u;
    asm("cvt.rna.tf32.f32 %0, %1;" : "=r"(u) : "f"(x));
    return __uint_as_float(u);
}
__device__ __forceinline__ float4 ftf4(float4 v) {
    return make_float4(ftf(v.x), ftf(v.y), ftf(v.z), ftf(v.w));
}
__device__ __forceinline__ void mma_tf32(float* c, const uint32_t* a, const uint32_t* b) {
    asm volatile(
        "mma.sync.aligned.m16n8k8.row.col.f32.tf32.tf32.f32 "
        "{%0,%1,%2,%3},{%4,%5,%6,%7},{%8,%9},{%0,%1,%2,%3};\n"
        : "+f"(c[0]), "+f"(c[1]), "+f"(c[2]), "+f"(c[3])
        : "r"(a[0]), "r"(a[1]), "r"(a[2]), "r"(a[3]), "r"(b[0]), "r"(b[1]));
}
__device__ __forceinline__ void split_tf32(float x, uint32_t& hi, uint32_t& lo) {
    float h = ftf(x);
    hi = __float_as_uint(h);
    lo = __float_as_uint(ftf(x - h));
}
#define U(x) __float_as_uint(x)

// ---------------- tf32 GEMM: 128x128 tile, k-slab 32, smem double buffer --
#define GPA 36
#define GPB 136
__global__ __launch_bounds__(256) void gemm512_tc(const float* __restrict__ Aext,
    const float* __restrict__ B0, const float* __restrict__ B1,
    const float* __restrict__ B2, float* __restrict__ Cext, int modeBase)
{
    extern __shared__ float smg[];
    float* As = smg;                    // 2 x 128*36
    float* Bs = smg + 2 * 128 * GPA;    // 2 x 32*136

    int mode = modeBase + blockIdx.z;
    const float* A  = (mode == 3) ? d_O : Aext;
    const float* Bm = (mode == 1) ? B1 : (mode == 2) ? B2 : B0;
    float* C = (mode == 0) ? d_Q : (mode == 1) ? d_K : (mode == 2) ? d_V : Cext;

    int tid = threadIdx.x, lane = tid & 31, w = tid >> 5;
    int grp = lane >> 2, t4 = lane & 3;
    int wm = w & 3, wn = w >> 2;
    int m0 = blockIdx.y * 128, n0 = blockIdx.x * 128;

    int arr[4], arc[4], brr[4], brc[4];
#pragma unroll
    for (int ii = 0; ii < 4; ii++) {
        int i = tid + ii * 256;
        arr[ii] = i >> 3;  arc[ii] = (i & 7) * 4;    // A: 128r x 32k
        brr[ii] = i >> 5;  brc[ii] = (i & 31) * 4;   // B: 32k x 128n
    }

    float acc[2][8][4];
#pragma unroll
    for (int mt = 0; mt < 2; mt++)
#pragma unroll
        for (int nt = 0; nt < 8; nt++)
#pragma unroll
            for (int r = 0; r < 4; r++) acc[mt][nt][r] = 0.f;

    float4 areg[4], breg[4];
#pragma unroll
    for (int ii = 0; ii < 4; ii++) {
        areg[ii] = *(const float4*)(A + (size_t)(m0 + arr[ii]) * 512 + arc[ii]);
        breg[ii] = *(const float4*)(Bm + (size_t)brr[ii] * 512 + n0 + brc[ii]);
    }
#pragma unroll
    for (int ii = 0; ii < 4; ii++) {
        *(float4*)(&As[arr[ii] * GPA + arc[ii]]) = ftf4(areg[ii]);
        *(float4*)(&Bs[brr[ii] * GPB + brc[ii]]) = ftf4(breg[ii]);
    }
    __syncthreads();

    for (int s = 0; s < 16; s++) {
        float* Ab = As + (s & 1) * 128 * GPA;
        float* Bb = Bs + (s & 1) * 32 * GPB;
        if (s < 15) {
            int k0 = (s + 1) * 32;
#pragma unroll
            for (int ii = 0; ii < 4; ii++) {
                areg[ii] = *(const float4*)(A + (size_t)(m0 + arr[ii]) * 512 + k0 + arc[ii]);
                breg[ii] = *(const float4*)(Bm + (size_t)(k0 + brr[ii]) * 512 + n0 + brc[ii]);
            }
        }
#pragma unroll
        for (int ks = 0; ks < 4; ks++) {
            int kb = ks * 8;
            uint32_t af[2][4], bf[8][2];
#pragma unroll
            for (int mt = 0; mt < 2; mt++) {
                int row = wm * 32 + mt * 16 + grp;
                af[mt][0] = U(Ab[row * GPA + kb + t4]);
                af[mt][1] = U(Ab[(row + 8) * GPA + kb + t4]);
                af[mt][2] = U(Ab[row * GPA + kb + t4 + 4]);
                af[mt][3] = U(Ab[(row + 8) * GPA + kb + t4 + 4]);
            }
#pragma unroll
            for (int nt = 0; nt < 8; nt++) {
                int col = wn * 64 + nt * 8 + grp;
                bf[nt][0] = U(Bb[(kb + t4) * GPB + col]);
                bf[nt][1] = U(Bb[(kb + t4 + 4) * GPB + col]);
            }
#pragma unroll
            for (int mt = 0; mt < 2; mt++)
#pragma unroll
                for (int nt = 0; nt < 8; nt++)
                    mma_tf32(acc[mt][nt], af[mt], bf[nt]);
        }
        if (s < 15) {
            float* An = As + ((s + 1) & 1) * 128 * GPA;
            float* Bn = Bs + ((s + 1) & 1) * 32 * GPB;
#pragma unroll
            for (int ii = 0; ii < 4; ii++) {
                *(float4*)(&An[arr[ii] * GPA + arc[ii]]) = ftf4(areg[ii]);
                *(float4*)(&Bn[brr[ii] * GPB + brc[ii]]) = ftf4(breg[ii]);
            }
        }
        __syncthreads();
    }
#pragma unroll
    for (int mt = 0; mt < 2; mt++)
#pragma unroll
        for (int nt = 0; nt < 8; nt++) {
            int row = m0 + wm * 32 + mt * 16 + grp;
            int col = n0 + wn * 64 + nt * 8 + 2 * t4;
            *(float2*)(C + (size_t)row * 512 + col) =
                make_float2(acc[mt][nt][0], acc[mt][nt][1]);
            *(float2*)(C + (size_t)(row + 8) * 512 + col) =
                make_float2(acc[mt][nt][2], acc[mt][nt][3]);
        }
}

// ---------------- gate (unchanged) ----------------
__global__ __launch_bounds__(256) void gate_kernel(const float* __restrict__ x,
                                                   const float* __restrict__ Wg)
{
    int w = threadIdx.x >> 5, lane = threadIdx.x & 31;
    int row = blockIdx.x * 8 + w;
    float p0 = 0, p1 = 0, p2 = 0;
#pragma unroll
    for (int c = 0; c < 4; c++) {
        int d = c * 128 + lane * 4;
        float4 xv = *(const float4*)(x + (size_t)row * 512 + d);
        p0 += xv.x * Wg[d * 3]     + xv.y * Wg[d * 3 + 3] +
              xv.z * Wg[d * 3 + 6] + xv.w * Wg[d * 3 + 9];
        p1 += xv.x * Wg[d * 3 + 1] + xv.y * Wg[d * 3 + 4] +
              xv.z * Wg[d * 3 + 7] + xv.w * Wg[d * 3 + 10];
        p2 += xv.x * Wg[d * 3 + 2] + xv.y * Wg[d * 3 + 5] +
              xv.z * Wg[d * 3 + 8] + xv.w * Wg[d * 3 + 11];
    }
#pragma unroll
    for (int o = 16; o; o >>= 1) {
        p0 += __shfl_xor_sync(0xffffffffu, p0, o);
        p1 += __shfl_xor_sync(0xffffffffu, p1, o);
        p2 += __shfl_xor_sync(0xffffffffu, p2, o);
    }
    if (lane == 0) {
        d_G[row * 3 + 0] = 1.f / (1.f + expf(-p0));
        d_G[row * 3 + 1] = 1.f / (1.f + expf(-p1));
        d_G[row * 3 + 2] = 1.f / (1.f + expf(-p2));
    }
}

// ---------------- compressed K/V means (unchanged) ----------------
__global__ __launch_bounds__(256) void compress_kernel()
{
    int idx = blockIdx.x * 256 + threadIdx.x;
    int d = idx & 63, n = (idx >> 6) & 127, h = (idx >> 13) & 7, b = idx >> 16;
    const float* kp = d_K + (size_t)(b * SEQ + n * 32) * 512 + h * 64 + d;
    const float* vp = d_V + (size_t)(b * SEQ + n * 32) * 512 + h * 64 + d;
    float ks = 0, vs = 0;
#pragma unroll
    for (int r = 0; r < 32; r++) { ks += kp[r * 512]; vs += vp[r * 512]; }
    d_KC[idx] = ks * (1.f / 32.f);
    d_VC[idx] = vs * (1.f / 32.f);
}

// ---------------- compressed attention + top-k (Q pre-split to hi/lo) -----
#define CQ2 136
#define CK 72
#define CS 132
__global__ __launch_bounds__(256) void cmp_attn_mma()
{
    extern __shared__ float sm[];
    float* qs2  = sm;                  // 64*136 (hi,lo pairs)
    float* kv   = qs2 + 64 * CQ2;      // 128*72 (raw Kc, then Vc)
    float* ps   = kv + 128 * CK;       // 64*132
    float* redm = ps + 64 * CS;        // 64*4
    float* reds = redm + 256;          // 64*4
    float* impb = reds + 256;          // 64

    int g = blockIdx.x, h = blockIdx.y, b = blockIdx.z;
    int tid = threadIdx.x, lane = tid & 31, w = tid >> 5;
    int grp = lane >> 2, t4 = lane & 3;
    int wm = w & 1, wn = w >> 1;
    int qbase = g * 64;

    // Q: load + split once into paired (hi,lo)
    for (int i = tid; i < 4096; i += 256) {
        int r = i >> 6, col = i & 63;
        float v = d_Q[(size_t)(b * SEQ + qbase + r) * 512 + h * 64 + col];
        uint32_t hi, lo;
        split_tf32(v, hi, lo);
        *(float2*)(&qs2[r * CQ2 + 2 * col]) =
            make_float2(__uint_as_float(hi), __uint_as_float(lo));
    }
    int cbase = ((b * NH + h) * NC) * HD;
    for (int i = tid; i < 2048; i += 256) {
        int r = i >> 4, d4 = (i & 15) * 4;
        float4 v = *(const float4*)(d_KC + cbase + r * 64 + d4);
        *(float4*)(&kv[r * CK + d4]) = v;
    }
    __syncthreads();

    float s[2][4][4];
#pragma unroll
    for (int mt = 0; mt < 2; mt++)
#pragma unroll
        for (int nt = 0; nt < 4; nt++)
#pragma unroll
            for (int r = 0; r < 4; r++) s[mt][nt][r] = 0.f;
#pragma unroll
    for (int ks = 0; ks < 8; ks++) {
        int kk = ks * 8;
        uint32_t ah[2][4], al[2][4], bh[4][2], bl[4][2];
#pragma unroll
        for (int mt = 0; mt < 2; mt++) {
            int row = wm * 32 + mt * 16 + grp;
            float2 p0 = *(float2*)(&qs2[row * CQ2 + 2 * (kk + t4)]);
            float2 p1 = *(float2*)(&qs2[(row + 8) * CQ2 + 2 * (kk + t4)]);
            float2 p2 = *(float2*)(&qs2[row * CQ2 + 2 * (kk + t4 + 4)]);
            float2 p3 = *(float2*)(&qs2[(row + 8) * CQ2 + 2 * (kk + t4 + 4)]);
            ah[mt][0] = U(p0.x); al[mt][0] = U(p0.y);
            ah[mt][1] = U(p1.x); al[mt][1] = U(p1.y);
            ah[mt][2] = U(p2.x); al[mt][2] = U(p2.y);
            ah[mt][3] = U(p3.x); al[mt][3] = U(p3.y);
        }
#pragma unroll
        for (int nt = 0; nt < 4; nt++) {
            int key = wn * 32 + nt * 8 + grp;
            split_tf32(kv[key * CK + kk + t4],     bh[nt][0], bl[nt][0]);
            split_tf32(kv[key * CK + kk + t4 + 4], bh[nt][1], bl[nt][1]);
        }
#pragma unroll
        for (int mt = 0; mt < 2; mt++)
#pragma unroll
            for (int nt = 0; nt < 4; nt++) {
                mma_tf32(s[mt][nt], ah[mt], bl[nt]);
                mma_tf32(s[mt][nt], al[mt], bh[nt]);
                mma_tf32(s[mt][nt], ah[mt], bh[nt]);
            }
    }

    int nval[2][2];
#pragma unroll
    for (int mt = 0; mt < 2; mt++)
#pragma unroll
        for (int hf = 0; hf < 2; hf++) {
            int pos = qbase + wm * 32 + mt * 16 + grp + hf * 8;
            nval[mt][hf] = (pos >= 31) ? ((pos - 31) >> 5) + 1 : 0;
        }
#pragma unroll
    for (int mt = 0; mt < 2; mt++)
#pragma unroll
        for (int nt = 0; nt < 4; nt++)
#pragma unroll
            for (int r = 0; r < 4; r++) {
                int c = wn * 32 + nt * 8 + 2 * t4 + (r & 1);
                bool valid = c < nval[mt][r >> 1];
                s[mt][nt][r] = valid ? s[mt][nt][r] * 0.125f : -1e30f;
            }

#pragma unroll
    for (int mt = 0; mt < 2; mt++)
#pragma unroll
        for (int hf = 0; hf < 2; hf++) {
            float rm = -1e30f;
#pragma unroll
            for (int nt = 0; nt < 4; nt++)
                rm = fmaxf(rm, fmaxf(s[mt][nt][2 * hf], s[mt][nt][2 * hf + 1]));
            rm = fmaxf(rm, __shfl_xor_sync(0xffffffffu, rm, 1));
            rm = fmaxf(rm, __shfl_xor_sync(0xffffffffu, rm, 2));
            if (t4 == 0)
                redm[(wm * 32 + mt * 16 + grp + hf * 8) * 4 + wn] = rm;
        }
    __syncthreads();

    for (int i = tid; i < 2048; i += 256) {
        int r = i >> 4, d4 = (i & 15) * 4;
        float4 v = *(const float4*)(d_VC + cbase + r * 64 + d4);
        *(float4*)(&kv[r * CK + d4]) = v;
    }
#pragma unroll
    for (int mt = 0; mt < 2; mt++)
#pragma unroll
        for (int hf = 0; hf < 2; hf++) {
            int row = wm * 32 + mt * 16 + grp + hf * 8;
            float4 rmv = *(float4*)(&redm[row * 4]);
            float gmax = fmaxf(fmaxf(rmv.x, rmv.y), fmaxf(rmv.z, rmv.w));
            float rs = 0.f;
#pragma unroll
            for (int nt = 0; nt < 4; nt++) {
                float e0 = __expf(s[mt][nt][2 * hf]     - gmax);
                float e1 = __expf(s[mt][nt][2 * hf + 1] - gmax);
                s[mt][nt][2 * hf] = e0;
                s[mt][nt][2 * hf + 1] = e1;
                rs += e0 + e1;
            }
            rs += __shfl_xor_sync(0xffffffffu, rs, 1);
            rs += __shfl_xor_sync(0xffffffffu, rs, 2);
            if (t4 == 0) reds[row * 4 + wn] = rs;
        }
    __syncthreads();

#pragma unroll
    for (int mt = 0; mt < 2; mt++)
#pragma unroll
        for (int hf = 0; hf < 2; hf++) {
            int row = wm * 32 + mt * 16 + grp + hf * 8;
            float4 rsv = *(float4*)(&reds[row * 4]);
            float tot = rsv.x + rsv.y + rsv.z + rsv.w;
            float inv = (nval[mt][hf] > 0) ? 1.f / tot : 0.f;
#pragma unroll
            for (int nt = 0; nt < 4; nt++) {
                int col = wn * 32 + nt * 8 + 2 * t4;
                ps[row * CS + col]     = s[mt][nt][2 * hf]     * inv;
                ps[row * CS + col + 1] = s[mt][nt][2 * hf + 1] * inv;
            }
        }
    __syncthreads();

    float o[2][2][4];
#pragma unroll
    for (int mt = 0; mt < 2; mt++)
#pragma unroll
        for (int nt = 0; nt < 2; nt++)
#pragma unroll
            for (int r = 0; r < 4; r++) o[mt][nt][r] = 0.f;
#pragma unroll
    for (int ks = 0; ks < 16; ks++) {
        int kk = ks * 8;
        uint32_t af[2][4], bf[2][2];
#pragma unroll
        for (int mt = 0; mt < 2; mt++) {
            int row = wm * 32 + mt * 16 + grp;
            af[mt][0] = U(ftf(ps[row * CS + kk + t4]));
            af[mt][1] = U(ftf(ps[(row + 8) * CS + kk + t4]));
            af[mt][2] = U(ftf(ps[row * CS + kk + t4 + 4]));
            af[mt][3] = U(ftf(ps[(row + 8) * CS + kk + t4 + 4]));
        }
#pragma unroll
        for (int nt = 0; nt < 2; nt++) {
            int dcol = wn * 16 + nt * 8 + grp;
            bf[nt][0] = U(ftf(kv[(kk + t4) * CK + dcol]));
            bf[nt][1] = U(ftf(kv[(kk + t4 + 4) * CK + dcol]));
        }
#pragma unroll
        for (int mt = 0; mt < 2; mt++)
#pragma unroll
            for (int nt = 0; nt < 2; nt++)
                mma_tf32(o[mt][nt], af[mt], bf[nt]);
    }

#pragma unroll
    for (int mt = 0; mt < 2; mt++)
#pragma unroll
        for (int hf = 0; hf < 2; hf++) {
            int qp = qbase + wm * 32 + mt * 16 + grp + hf * 8;
            float g0 = d_G[(b * SEQ + qp) * 3 + 0];
#pragma unroll
            for (int nt = 0; nt < 2; nt++) {
                int dcol = wn * 16 + nt * 8 + 2 * t4;
                size_t ob = (size_t)(b * SEQ + qp) * 512 + h * 64 + dcol;
                *(float2*)(d_O + ob) = make_float2(o[mt][nt][2 * hf] * g0,
                                                   o[mt][nt][2 * hf + 1] * g0);
            }
        }
    __syncthreads();

    if (tid < 64) {
        float v = 0.f;
        for (int q = 0; q < 64; q++)
            v += ps[q * CS + 2 * tid] + ps[q * CS + 2 * tid + 1];
        impb[tid] = v;
    }
    __syncthreads();
    if (w == 0) {
        int j0 = lane, j1 = lane + 32;
        float v0 = (j0 <= g) ? impb[j0] + (j0 == g ? 1e9f : 0.f) : -1e30f;
        float v1 = (j1 <= g) ? impb[j1] + (j1 == g ? 1e9f : 0.f) : -1e30f;
        int selbase = ((b * NH + h) * NS + g) * TOPK;
        for (int r = 0; r < TOPK; r++) {
            float bv; int bi;
            if (v0 >= v1) { bv = v0; bi = j0; } else { bv = v1; bi = j1; }
#pragma unroll
            for (int o2 = 16; o2; o2 >>= 1) {
                float ov = __shfl_xor_sync(0xffffffffu, bv, o2);
                int   oi = __shfl_xor_sync(0xffffffffu, bi, o2);
                if (ov > bv || (ov == bv && oi < bi)) { bv = ov; bi = oi; }
            }
            if (lane == 0) d_SEL[selbase + r] = bi;
            if (bi == j0) v0 = -3e30f;
            if (bi == j1) v1 = -3e30f;
        }
    }
}

// ---------------- fused sel+win flash attention (R7 proven version) --------
#define QP 72
#define KP 68
#define VP 72
#define PP 72
__global__ __launch_bounds__(256) void selwin_fused()
{
    extern __shared__ float sm[];
    float* qs   = sm;                 // 64*72 paired
    float* Ks   = qs + 64 * QP;       // 64*68
    float* Vs   = Ks + 64 * KP;       // 64*72
    float* ps   = Vs + 64 * VP;       // 64*72 paired
    float* redm = ps + 64 * PP;       // 64*4
    float* reds = redm + 256;         // 64*4

    int g = blockIdx.x, hh = blockIdx.y, b = blockIdx.z;
    int tid = threadIdx.x, lane = tid & 31, w = tid >> 5;
    int grp = lane >> 2, t4 = lane & 3;
    int wm = w & 1, wn = w >> 1;
    int qbase = g * 64;

#pragma unroll
    for (int ii = 0; ii < 2; ii++) {
        int i = tid + ii * 256;
        int r = i >> 3, g8 = (i & 7) * 8;
        const float* src = d_Q + (size_t)(b * SEQ + qbase + r) * 512 + hh * 64 + g8;
        float4 lo = *(const float4*)src;
        float4 hi = *(const float4*)(src + 4);
        float2* dst = (float2*)(&qs[r * QP + g8]);
        dst[0] = make_float2(ftf(lo.x), ftf(hi.x));
        dst[1] = make_float2(ftf(lo.y), ftf(hi.y));
        dst[2] = make_float2(ftf(lo.z), ftf(hi.z));
        dst[3] = make_float2(ftf(lo.w), ftf(hi.w));
    }

    int selbase = ((b * NH + hh) * NS + g) * TOPK;
    int kblist[25];
    int nsel = 0;
#pragma unroll
    for (int it = 0; it < TOPK; it++) {
        int kb = d_SEL[selbase + it];
        if (kb <= g) kblist[nsel++] = kb;
    }
    int ntot = nsel;
    {
        int st = (g > 8) ? g - 8 : 0;
        for (int kb = st; kb <= g; kb++) kblist[ntot++] = kb;
    }

    float gv1[2][2], gv2[2][2];
#pragma unroll
    for (int mt = 0; mt < 2; mt++)
#pragma unroll
        for (int hf = 0; hf < 2; hf++) {
            int qp = qbase + wm * 32 + mt * 16 + grp + hf * 8;
            gv1[mt][hf] = d_G[(b * SEQ + qp) * 3 + 1];
            gv2[mt][hf] = d_G[(b * SEQ + qp) * 3 + 2];
        }

    float out_acc[2][2][4], o[2][2][4];
#pragma unroll
    for (int mt = 0; mt < 2; mt++)
#pragma unroll
        for (int nt = 0; nt < 2; nt++)
#pragma unroll
            for (int r = 0; r < 4; r++) { out_acc[mt][nt][r] = 0.f; o[mt][nt][r] = 0.f; }
    float mst[2][2], lst[2][2];
#pragma unroll
    for (int mt = 0; mt < 2; mt++)
#pragma unroll
        for (int hf = 0; hf < 2; hf++) { mst[mt][hf] = -1e30f; lst[mt][hf] = 0.f; }

    float4 kreg[4], vreg[4];
    int pr = tid >> 4, pd4 = (tid & 15) * 4;
    {
        size_t kbase = (size_t)(b * SEQ + kblist[0] * 64) * 512 + hh * 64;
#pragma unroll
        for (int j = 0; j < 4; j++) {
            kreg[j] = *(const float4*)(d_K + kbase + (size_t)(pr + j * 16) * 512 + pd4);
            vreg[j] = *(const float4*)(d_V + kbase + (size_t)(pr + j * 16) * 512 + pd4);
        }
#pragma unroll
        for (int j = 0; j < 4; j++) {
            int r = pr + j * 16;
            *(float4*)(&Ks[r * KP + pd4]) = ftf4(kreg[j]);
            *(float4*)(&Vs[r * VP + pd4]) = ftf4(vreg[j]);
        }
        int nb = (ntot > 1) ? 1 : 0;
        size_t kbase1 = (size_t)(b * SEQ + kblist[nb] * 64) * 512 + hh * 64;
#pragma unroll
        for (int j = 0; j < 4; j++) {
            kreg[j] = *(const float4*)(d_K + kbase1 + (size_t)(pr + j * 16) * 512 + pd4);
            vreg[j] = *(const float4*)(d_V + kbase1 + (size_t)(pr + j * 16) * 512 + pd4);
        }
    }
    __syncthreads();

    int posA = ((t4 & 1) << 2) + (t4 >> 1);

    for (int t = 0; t < ntot; t++) {
        if (t == nsel) {
#pragma unroll
            for (int mt = 0; mt < 2; mt++)
#pragma unroll
                for (int hf = 0; hf < 2; hf++) {
                    float inv = gv1[mt][hf] / lst[mt][hf];
#pragma unroll
                    for (int nt = 0; nt < 2; nt++) {
                        out_acc[mt][nt][2 * hf]     += o[mt][nt][2 * hf]     * inv;
                        out_acc[mt][nt][2 * hf + 1] += o[mt][nt][2 * hf + 1] * inv;
                        o[mt][nt][2 * hf] = 0.f; o[mt][nt][2 * hf + 1] = 0.f;
                    }
                    mst[mt][hf] = -1e30f; lst[mt][hf] = 0.f;
                }
        }
        int kb = kblist[t];
        bool winph = (t >= nsel);
        bool more = (t + 1 < ntot);
        int nidx = (t + 2 < ntot) ? t + 2 : ntot - 1;
        size_t nbase = (size_t)(b * SEQ + kblist[nidx] * 64) * 512 + hh * 64;

        float s[2][2][4];
#pragma unroll
        for (int mt = 0; mt < 2; mt++)
#pragma unroll
            for (int nt = 0; nt < 2; nt++)
#pragma unroll
                for (int r = 0; r < 4; r++) s[mt][nt][r] = 0.f;
#pragma unroll
        for (int ks = 0; ks < 8; ks++) {
            int kk = ks * 8;
            uint32_t af[2][4], bf[2][2];
#pragma unroll
            for (int mt = 0; mt < 2; mt++) {
                int row = wm * 32 + mt * 16 + grp;
                float2 a0 = *(float2*)(&qs[row * QP + kk + 2 * t4]);
                float2 a1 = *(float2*)(&qs[(row + 8) * QP + kk + 2 * t4]);
                af[mt][0] = U(a0.x); af[mt][2] = U(a0.y);
                af[mt][1] = U(a1.x); af[mt][3] = U(a1.y);
            }
#pragma unroll
            for (int nt = 0; nt < 2; nt++) {
                int key = wn * 16 + nt * 8 + grp;
                bf[nt][0] = U(Ks[key * KP + kk + t4]);
                bf[nt][1] = U(Ks[key * KP + kk + t4 + 4]);
            }
#pragma unroll
            for (int mt = 0; mt < 2; mt++)
#pragma unroll
                for (int nt = 0; nt < 2; nt++)
                    mma_tf32(s[mt][nt], af[mt], bf[nt]);
        }

#pragma unroll
        for (int mt = 0; mt < 2; mt++)
#pragma unroll
            for (int nt = 0; nt < 2; nt++)
#pragma unroll
                for (int r = 0; r < 4; r++) {
                    int qp = qbase + wm * 32 + mt * 16 + grp + (r >> 1) * 8;
                    int kp = kb * 64 + wn * 16 + nt * 8 + 2 * t4 + (r & 1);
                    bool valid = (kp <= qp) && (!winph || (kp + 512 > qp));
                    s[mt][nt][r] = valid ? s[mt][nt][r] * 0.125f : -1e30f;
                }

#pragma unroll
        for (int mt = 0; mt < 2; mt++)
#pragma unroll
            for (int hf = 0; hf < 2; hf++) {
                float rm = fmaxf(fmaxf(s[mt][0][2 * hf], s[mt][0][2 * hf + 1]),
                                 fmaxf(s[mt][1][2 * hf], s[mt][1][2 * hf + 1]));
                rm = fmaxf(rm, __shfl_xor_sync(0xffffffffu, rm, 1));
                rm = fmaxf(rm, __shfl_xor_sync(0xffffffffu, rm, 2));
                if (t4 == 0)
                    redm[(wm * 32 + mt * 16 + grp + hf * 8) * 4 + wn] = rm;
            }
        __syncthreads();

        if (more) {
#pragma unroll
            for (int j = 0; j < 4; j++)
                *(float4*)(&Ks[(pr + j * 16) * KP + pd4]) = ftf4(kreg[j]);
#pragma unroll
            for (int j = 0; j < 4; j++)
                kreg[j] = *(const float4*)(d_K + nbase + (size_t)(pr + j * 16) * 512 + pd4);
        }

        float corr[2][2], mnew[2][2];
#pragma unroll
        for (int mt = 0; mt < 2; mt++)
#pragma unroll
            for (int hf = 0; hf < 2; hf++) {
                int row = wm * 32 + mt * 16 + grp + hf * 8;
                float4 rmv = *(float4*)(&redm[row * 4]);
                float gmax = fmaxf(fmaxf(rmv.x, rmv.y), fmaxf(rmv.z, rmv.w));
                float mn = fmaxf(mst[mt][hf], gmax);
                mnew[mt][hf] = mn;
                corr[mt][hf] = __expf(mst[mt][hf] - mn);
            }

#pragma unroll
        for (int mt = 0; mt < 2; mt++)
#pragma unroll
            for (int hf = 0; hf < 2; hf++) {
                int rowl = wm * 32 + mt * 16 + grp + hf * 8;
                float mn = mnew[mt][hf];
                float rs = 0.f;
#pragma unroll
                for (int nt = 0; nt < 2; nt++) {
                    float p0 = __expf(s[mt][nt][2 * hf]     - mn);
                    float p1 = __expf(s[mt][nt][2 * hf + 1] - mn);
                    rs += p0 + p1;
                    int gb = wn * 16 + nt * 8;
                    ps[rowl * PP + gb + posA]     = ftf(p0);
                    ps[rowl * PP + gb + posA + 2] = ftf(p1);
                }
                rs += __shfl_xor_sync(0xffffffffu, rs, 1);
                rs += __shfl_xor_sync(0xffffffffu, rs, 2);
                if (t4 == 0) reds[rowl * 4 + wn] = rs;
            }
        __syncthreads();

#pragma unroll
        for (int mt = 0; mt < 2; mt++)
#pragma unroll
            for (int hf = 0; hf < 2; hf++) {
                int row = wm * 32 + mt * 16 + grp + hf * 8;
                float4 rsv = *(float4*)(&reds[row * 4]);
                float ls = rsv.x + rsv.y + rsv.z + rsv.w;
                float cr = corr[mt][hf];
                lst[mt][hf] = lst[mt][hf] * cr + ls;
                mst[mt][hf] = mnew[mt][hf];
#pragma unroll
                for (int nt = 0; nt < 2; nt++) {
                    o[mt][nt][2 * hf]     *= cr;
                    o[mt][nt][2 * hf + 1] *= cr;
                }
            }

#pragma unroll
        for (int ks = 0; ks < 8; ks++) {
            int kk = ks * 8;
            uint32_t af[2][4], bf[2][2];
#pragma unroll
            for (int mt = 0; mt < 2; mt++) {
                int row = wm * 32 + mt * 16 + grp;
                float2 p0 = *(float2*)(&ps[row * PP + kk + 2 * t4]);
                float2 p1 = *(float2*)(&ps[(row + 8) * PP + kk + 2 * t4]);
                af[mt][0] = U(p0.x); af[mt][2] = U(p0.y);
                af[mt][1] = U(p1.x); af[mt][3] = U(p1.y);
            }
#pragma unroll
            for (int nt = 0; nt < 2; nt++) {
                int dcol = wn * 16 + nt * 8 + grp;
                bf[nt][0] = U(Vs[(kk + t4) * VP + dcol]);
                bf[nt][1] = U(Vs[(kk + t4 + 4) * VP + dcol]);
            }
#pragma unroll
            for (int mt = 0; mt < 2; mt++)
#pragma unroll
                for (int nt = 0; nt < 2; nt++)
                    mma_tf32(o[mt][nt], af[mt], bf[nt]);
        }
        __syncthreads();

        if (more) {
#pragma unroll
            for (int j = 0; j < 4; j++)
                *(float4*)(&Vs[(pr + j * 16) * VP + pd4]) = ftf4(vreg[j]);
#pragma unroll
            for (int j = 0; j < 4; j++)
                vreg[j] = *(const float4*)(d_V + nbase + (size_t)(pr + j * 16) * 512 + pd4);
        }
    }

#pragma unroll
    for (int mt = 0; mt < 2; mt++)
#pragma unroll
        for (int hf = 0; hf < 2; hf++) {
            int qp = qbase + wm * 32 + mt * 16 + grp + hf * 8;
            float inv = gv2[mt][hf] / lst[mt][hf];
#pragma unroll
            for (int nt = 0; nt < 2; nt++) {
                int dcol = wn * 16 + nt * 8 + 2 * t4;
                size_t ob = (size_t)(b * SEQ + qp) * 512 + hh * 64 + dcol;
                float2 cur = *(float2*)(d_O + ob);
                cur.x += out_acc[mt][nt][2 * hf]     + o[mt][nt][2 * hf]     * inv;
                cur.y += out_acc[mt][nt][2 * hf + 1] + o[mt][nt][2 * hf + 1] * inv;
                *(float2*)(d_O + ob) = cur;
            }
        }
}

// ---------------------------------------------------------------------------
extern "C" void kernel_launch(void* const* d_in, const int* in_sizes, int n_in,
                              void* d_out, int out_size)
{
    const float* x  = (const float*)d_in[0];
    const float* Wq = (const float*)d_in[1];
    const float* Wk = (const float*)d_in[2];
    const float* Wv = (const float*)d_in[3];
    const float* Wo = (const float*)d_in[4];
    const float* Wg = (const float*)d_in[5];
    float* y = (float*)d_out;

    // gemm smem: 2*128*36 + 2*32*136 floats = 71680 bytes
    cudaFuncSetAttribute(gemm512_tc,
                         cudaFuncAttributeMaxDynamicSharedMemorySize, 71680);
    // cmp smem: 64*136 + 128*72 + 64*132 + 256 + 256 + 64 floats = 107776 B
    cudaFuncSetAttribute(cmp_attn_mma,
                         cudaFuncAttributeMaxDynamicSharedMemorySize, 107776);
    cudaFuncSetAttribute(selwin_fused,
                         cudaFuncAttributeMaxDynamicSharedMemorySize, 74752);

    gemm512_tc<<<dim3(4, 64, 3), 256, 71680>>>(x, Wq, Wk, Wv, nullptr, 0);
    gate_kernel<<<NROWS / 8, 256>>>(x, Wg);
    compress_kernel<<<(BATCH * NH * NC * HD) / 256, 256>>>();
    cmp_attn_mma<<<dim3(64, 8, 2), 256, 107776>>>();
    selwin_fused<<<dim3(64, 8, 2), 256, 74752>>>();
    gemm512_tc<<<dim3(4, 64, 1), 256, 71680>>>(nullptr, Wo, nullptr, nullptr, y, 3);
}

// round 11
// speedup vs baseline: 1.0540x; 1.0338x over previous
#include <cuda_runtime.h>
#include <math.h>
#include <stdint.h>

#define BATCH   2
#define SEQ     4096
#define DMODEL  512
#define NH      8
#define HD      64
#define NC      128
#define NS      64
#define TOPK    16
#define NROWS   (BATCH*SEQ)

// ---------------- scratch ----------------
__device__ float d_Q[NROWS*DMODEL];
__device__ float d_K[NROWS*DMODEL];
__device__ float d_V[NROWS*DMODEL];
__device__ float d_O[NROWS*DMODEL];
__device__ float d_KC[BATCH*NH*NC*HD];
__device__ float d_VC[BATCH*NH*NC*HD];
__device__ float d_G[NROWS*3];
__device__ int   d_SEL[BATCH*NH*NS*TOPK];

// ---------------- tf32 helpers ----------------
__device__ __forceinline__ float ftf(float x) {
    uint32_t u;
    asm("cvt.rna.tf32.f32 %0, %1;" : "=r"(u) : "f"(x));
    return __uint_as_float(u);
}
__device__ __forceinline__ float4 ftf4(float4 v) {
    return make_float4(ftf(v.x), ftf(v.y), ftf(v.z), ftf(v.w));
}
__device__ __forceinline__ void mma_tf32(float* c, const uint32_t* a, const uint32_t* b) {
    asm volatile(
        "mma.sync.aligned.m16n8k8.row.col.f32.tf32.tf32.f32 "
        "{%0,%1,%2,%3},{%4,%5,%6,%7},{%8,%9},{%0,%1,%2,%3};\n"
        : "+f"(c[0]), "+f"(c[1]), "+f"(c[2]), "+f"(c[3])
        : "r"(a[0]), "r"(a[1]), "r"(a[2]), "r"(a[3]), "r"(b[0]), "r"(b[1]));
}
__device__ __forceinline__ void split_tf32(float x, uint32_t& hi, uint32_t& lo) {
    float h = ftf(x);
    hi = __float_as_uint(h);
    lo = __float_as_uint(ftf(x - h));
}
#define U(x) __float_as_uint(x)

// ---------------- tf32 GEMM: 128x128 tile, k-slab 32, smem double buffer --
// (R10 version — measured ~9us faster than R7's 16-slab variant)
#define GPA 36
#define GPB 136
__global__ __launch_bounds__(256) void gemm512_tc(const float* __restrict__ Aext,
    const float* __restrict__ B0, const float* __restrict__ B1,
    const float* __restrict__ B2, float* __restrict__ Cext, int modeBase)
{
    extern __shared__ float smg[];
    float* As = smg;                    // 2 x 128*36
    float* Bs = smg + 2 * 128 * GPA;    // 2 x 32*136

    int mode = modeBase + blockIdx.z;
    const float* A  = (mode == 3) ? d_O : Aext;
    const float* Bm = (mode == 1) ? B1 : (mode == 2) ? B2 : B0;
    float* C = (mode == 0) ? d_Q : (mode == 1) ? d_K : (mode == 2) ? d_V : Cext;

    int tid = threadIdx.x, lane = tid & 31, w = tid >> 5;
    int grp = lane >> 2, t4 = lane & 3;
    int wm = w & 3, wn = w >> 2;
    int m0 = blockIdx.y * 128, n0 = blockIdx.x * 128;

    int arr[4], arc[4], brr[4], brc[4];
#pragma unroll
    for (int ii = 0; ii < 4; ii++) {
        int i = tid + ii * 256;
        arr[ii] = i >> 3;  arc[ii] = (i & 7) * 4;
        brr[ii] = i >> 5;  brc[ii] = (i & 31) * 4;
    }

    float acc[2][8][4];
#pragma unroll
    for (int mt = 0; mt < 2; mt++)
#pragma unroll
        for (int nt = 0; nt < 8; nt++)
#pragma unroll
            for (int r = 0; r < 4; r++) acc[mt][nt][r] = 0.f;

    float4 areg[4], breg[4];
#pragma unroll
    for (int ii = 0; ii < 4; ii++) {
        areg[ii] = *(const float4*)(A + (size_t)(m0 + arr[ii]) * 512 + arc[ii]);
        breg[ii] = *(const float4*)(Bm + (size_t)brr[ii] * 512 + n0 + brc[ii]);
    }
#pragma unroll
    for (int ii = 0; ii < 4; ii++) {
        *(float4*)(&As[arr[ii] * GPA + arc[ii]]) = ftf4(areg[ii]);
        *(float4*)(&Bs[brr[ii] * GPB + brc[ii]]) = ftf4(breg[ii]);
    }
    __syncthreads();

    for (int s = 0; s < 16; s++) {
        float* Ab = As + (s & 1) * 128 * GPA;
        float* Bb = Bs + (s & 1) * 32 * GPB;
        if (s < 15) {
            int k0 = (s + 1) * 32;
#pragma unroll
            for (int ii = 0; ii < 4; ii++) {
                areg[ii] = *(const float4*)(A + (size_t)(m0 + arr[ii]) * 512 + k0 + arc[ii]);
                breg[ii] = *(const float4*)(Bm + (size_t)(k0 + brr[ii]) * 512 + n0 + brc[ii]);
            }
        }
#pragma unroll
        for (int ks = 0; ks < 4; ks++) {
            int kb = ks * 8;
            uint32_t af[2][4], bf[8][2];
#pragma unroll
            for (int mt = 0; mt < 2; mt++) {
                int row = wm * 32 + mt * 16 + grp;
                af[mt][0] = U(Ab[row * GPA + kb + t4]);
                af[mt][1] = U(Ab[(row + 8) * GPA + kb + t4]);
                af[mt][2] = U(Ab[row * GPA + kb + t4 + 4]);
                af[mt][3] = U(Ab[(row + 8) * GPA + kb + t4 + 4]);
            }
#pragma unroll
            for (int nt = 0; nt < 8; nt++) {
                int col = wn * 64 + nt * 8 + grp;
                bf[nt][0] = U(Bb[(kb + t4) * GPB + col]);
                bf[nt][1] = U(Bb[(kb + t4 + 4) * GPB + col]);
            }
#pragma unroll
            for (int mt = 0; mt < 2; mt++)
#pragma unroll
                for (int nt = 0; nt < 8; nt++)
                    mma_tf32(acc[mt][nt], af[mt], bf[nt]);
        }
        if (s < 15) {
            float* An = As + ((s + 1) & 1) * 128 * GPA;
            float* Bn = Bs + ((s + 1) & 1) * 32 * GPB;
#pragma unroll
            for (int ii = 0; ii < 4; ii++) {
                *(float4*)(&An[arr[ii] * GPA + arc[ii]]) = ftf4(areg[ii]);
                *(float4*)(&Bn[brr[ii] * GPB + brc[ii]]) = ftf4(breg[ii]);
            }
        }
        __syncthreads();
    }
#pragma unroll
    for (int mt = 0; mt < 2; mt++)
#pragma unroll
        for (int nt = 0; nt < 8; nt++) {
            int row = m0 + wm * 32 + mt * 16 + grp;
            int col = n0 + wn * 64 + nt * 8 + 2 * t4;
            *(float2*)(C + (size_t)row * 512 + col) =
                make_float2(acc[mt][nt][0], acc[mt][nt][1]);
            *(float2*)(C + (size_t)(row + 8) * 512 + col) =
                make_float2(acc[mt][nt][2], acc[mt][nt][3]);
        }
}

// ---------------- gate ----------------
__global__ __launch_bounds__(256) void gate_kernel(const float* __restrict__ x,
                                                   const float* __restrict__ Wg)
{
    int w = threadIdx.x >> 5, lane = threadIdx.x & 31;
    int row = blockIdx.x * 8 + w;
    float p0 = 0, p1 = 0, p2 = 0;
#pragma unroll
    for (int c = 0; c < 4; c++) {
        int d = c * 128 + lane * 4;
        float4 xv = *(const float4*)(x + (size_t)row * 512 + d);
        p0 += xv.x * Wg[d * 3]     + xv.y * Wg[d * 3 + 3] +
              xv.z * Wg[d * 3 + 6] + xv.w * Wg[d * 3 + 9];
        p1 += xv.x * Wg[d * 3 + 1] + xv.y * Wg[d * 3 + 4] +
              xv.z * Wg[d * 3 + 7] + xv.w * Wg[d * 3 + 10];
        p2 += xv.x * Wg[d * 3 + 2] + xv.y * Wg[d * 3 + 5] +
              xv.z * Wg[d * 3 + 8] + xv.w * Wg[d * 3 + 11];
    }
#pragma unroll
    for (int o = 16; o; o >>= 1) {
        p0 += __shfl_xor_sync(0xffffffffu, p0, o);
        p1 += __shfl_xor_sync(0xffffffffu, p1, o);
        p2 += __shfl_xor_sync(0xffffffffu, p2, o);
    }
    if (lane == 0) {
        d_G[row * 3 + 0] = 1.f / (1.f + expf(-p0));
        d_G[row * 3 + 1] = 1.f / (1.f + expf(-p1));
        d_G[row * 3 + 2] = 1.f / (1.f + expf(-p2));
    }
}

// ---------------- compressed K/V means ----------------
__global__ __launch_bounds__(256) void compress_kernel()
{
    int idx = blockIdx.x * 256 + threadIdx.x;
    int d = idx & 63, n = (idx >> 6) & 127, h = (idx >> 13) & 7, b = idx >> 16;
    const float* kp = d_K + (size_t)(b * SEQ + n * 32) * 512 + h * 64 + d;
    const float* vp = d_V + (size_t)(b * SEQ + n * 32) * 512 + h * 64 + d;
    float ks = 0, vs = 0;
#pragma unroll
    for (int r = 0; r < 32; r++) { ks += kp[r * 512]; vs += vp[r * 512]; }
    d_KC[idx] = ks * (1.f / 32.f);
    d_VC[idx] = vs * (1.f / 32.f);
}

// ---------------- compressed attention + top-k (R7 proven: 3xTF32 QK) -----
#define CQ 68
#define CK 72
#define CS 132
__global__ __launch_bounds__(256) void cmp_attn_mma()
{
    extern __shared__ float sm[];
    float* qs   = sm;                  // 64*68  (raw fp32 Q)
    float* kv   = qs + 64 * CQ;        // 128*72 (raw Kc, then Vc)
    float* ps   = kv + 128 * CK;       // 64*132
    float* redm = ps + 64 * CS;        // 64*4
    float* reds = redm + 256;          // 64*4
    float* impb = reds + 256;          // 64

    int g = blockIdx.x, h = blockIdx.y, b = blockIdx.z;
    int tid = threadIdx.x, lane = tid & 31, w = tid >> 5;
    int grp = lane >> 2, t4 = lane & 3;
    int wm = w & 1, wn = w >> 1;
    int qbase = g * 64;

    for (int i = tid; i < 1024; i += 256) {
        int r = i >> 4, d4 = (i & 15) * 4;
        float4 v = *(const float4*)(d_Q + (size_t)(b * SEQ + qbase + r) * 512 + h * 64 + d4);
        *(float4*)(&qs[r * CQ + d4]) = v;
    }
    int cbase = ((b * NH + h) * NC) * HD;
    for (int i = tid; i < 2048; i += 256) {
        int r = i >> 4, d4 = (i & 15) * 4;
        float4 v = *(const float4*)(d_KC + cbase + r * 64 + d4);
        *(float4*)(&kv[r * CK + d4]) = v;
    }
    __syncthreads();

    float s[2][4][4];
#pragma unroll
    for (int mt = 0; mt < 2; mt++)
#pragma unroll
        for (int nt = 0; nt < 4; nt++)
#pragma unroll
            for (int r = 0; r < 4; r++) s[mt][nt][r] = 0.f;
#pragma unroll
    for (int ks = 0; ks < 8; ks++) {
        int kk = ks * 8;
        uint32_t ah[2][4], al[2][4], bh[4][2], bl[4][2];
#pragma unroll
        for (int mt = 0; mt < 2; mt++) {
            int row = wm * 32 + mt * 16 + grp;
            split_tf32(qs[row * CQ + kk + t4],           ah[mt][0], al[mt][0]);
            split_tf32(qs[(row + 8) * CQ + kk + t4],     ah[mt][1], al[mt][1]);
            split_tf32(qs[row * CQ + kk + t4 + 4],       ah[mt][2], al[mt][2]);
            split_tf32(qs[(row + 8) * CQ + kk + t4 + 4], ah[mt][3], al[mt][3]);
        }
#pragma unroll
        for (int nt = 0; nt < 4; nt++) {
            int key = wn * 32 + nt * 8 + grp;
            split_tf32(kv[key * CK + kk + t4],     bh[nt][0], bl[nt][0]);
            split_tf32(kv[key * CK + kk + t4 + 4], bh[nt][1], bl[nt][1]);
        }
#pragma unroll
        for (int mt = 0; mt < 2; mt++)
#pragma unroll
            for (int nt = 0; nt < 4; nt++) {
                mma_tf32(s[mt][nt], ah[mt], bl[nt]);
                mma_tf32(s[mt][nt], al[mt], bh[nt]);
                mma_tf32(s[mt][nt], ah[mt], bh[nt]);
            }
    }

    int nval[2][2];
#pragma unroll
    for (int mt = 0; mt < 2; mt++)
#pragma unroll
        for (int hf = 0; hf < 2; hf++) {
            int pos = qbase + wm * 32 + mt * 16 + grp + hf * 8;
            nval[mt][hf] = (pos >= 31) ? ((pos - 31) >> 5) + 1 : 0;
        }
#pragma unroll
    for (int mt = 0; mt < 2; mt++)
#pragma unroll
        for (int nt = 0; nt < 4; nt++)
#pragma unroll
            for (int r = 0; r < 4; r++) {
                int c = wn * 32 + nt * 8 + 2 * t4 + (r & 1);
                bool valid = c < nval[mt][r >> 1];
                s[mt][nt][r] = valid ? s[mt][nt][r] * 0.125f : -1e30f;
            }

#pragma unroll
    for (int mt = 0; mt < 2; mt++)
#pragma unroll
        for (int hf = 0; hf < 2; hf++) {
            float rm = -1e30f;
#pragma unroll
            for (int nt = 0; nt < 4; nt++)
                rm = fmaxf(rm, fmaxf(s[mt][nt][2 * hf], s[mt][nt][2 * hf + 1]));
            rm = fmaxf(rm, __shfl_xor_sync(0xffffffffu, rm, 1));
            rm = fmaxf(rm, __shfl_xor_sync(0xffffffffu, rm, 2));
            if (t4 == 0)
                redm[(wm * 32 + mt * 16 + grp + hf * 8) * 4 + wn] = rm;
        }
    __syncthreads();

    for (int i = tid; i < 2048; i += 256) {
        int r = i >> 4, d4 = (i & 15) * 4;
        float4 v = *(const float4*)(d_VC + cbase + r * 64 + d4);
        *(float4*)(&kv[r * CK + d4]) = v;
    }
#pragma unroll
    for (int mt = 0; mt < 2; mt++)
#pragma unroll
        for (int hf = 0; hf < 2; hf++) {
            int row = wm * 32 + mt * 16 + grp + hf * 8;
            float4 rmv = *(float4*)(&redm[row * 4]);
            float gmax = fmaxf(fmaxf(rmv.x, rmv.y), fmaxf(rmv.z, rmv.w));
            float rs = 0.f;
#pragma unroll
            for (int nt = 0; nt < 4; nt++) {
                float e0 = __expf(s[mt][nt][2 * hf]     - gmax);
                float e1 = __expf(s[mt][nt][2 * hf + 1] - gmax);
                s[mt][nt][2 * hf] = e0;
                s[mt][nt][2 * hf + 1] = e1;
                rs += e0 + e1;
            }
            rs += __shfl_xor_sync(0xffffffffu, rs, 1);
            rs += __shfl_xor_sync(0xffffffffu, rs, 2);
            if (t4 == 0) reds[row * 4 + wn] = rs;
        }
    __syncthreads();

#pragma unroll
    for (int mt = 0; mt < 2; mt++)
#pragma unroll
        for (int hf = 0; hf < 2; hf++) {
            int row = wm * 32 + mt * 16 + grp + hf * 8;
            float4 rsv = *(float4*)(&reds[row * 4]);
            float tot = rsv.x + rsv.y + rsv.z + rsv.w;
            float inv = (nval[mt][hf] > 0) ? 1.f / tot : 0.f;
#pragma unroll
            for (int nt = 0; nt < 4; nt++) {
                int col = wn * 32 + nt * 8 + 2 * t4;
                ps[row * CS + col]     = s[mt][nt][2 * hf]     * inv;
                ps[row * CS + col + 1] = s[mt][nt][2 * hf + 1] * inv;
            }
        }
    __syncthreads();

    float o[2][2][4];
#pragma unroll
    for (int mt = 0; mt < 2; mt++)
#pragma unroll
        for (int nt = 0; nt < 2; nt++)
#pragma unroll
            for (int r = 0; r < 4; r++) o[mt][nt][r] = 0.f;
#pragma unroll
    for (int ks = 0; ks < 16; ks++) {
        int kk = ks * 8;
        uint32_t af[2][4], bf[2][2];
#pragma unroll
        for (int mt = 0; mt < 2; mt++) {
            int row = wm * 32 + mt * 16 + grp;
            af[mt][0] = U(ftf(ps[row * CS + kk + t4]));
            af[mt][1] = U(ftf(ps[(row + 8) * CS + kk + t4]));
            af[mt][2] = U(ftf(ps[row * CS + kk + t4 + 4]));
            af[mt][3] = U(ftf(ps[(row + 8) * CS + kk + t4 + 4]));
        }
#pragma unroll
        for (int nt = 0; nt < 2; nt++) {
            int dcol = wn * 16 + nt * 8 + grp;
            bf[nt][0] = U(ftf(kv[(kk + t4) * CK + dcol]));
            bf[nt][1] = U(ftf(kv[(kk + t4 + 4) * CK + dcol]));
        }
#pragma unroll
        for (int mt = 0; mt < 2; mt++)
#pragma unroll
            for (int nt = 0; nt < 2; nt++)
                mma_tf32(o[mt][nt], af[mt], bf[nt]);
    }

#pragma unroll
    for (int mt = 0; mt < 2; mt++)
#pragma unroll
        for (int hf = 0; hf < 2; hf++) {
            int qp = qbase + wm * 32 + mt * 16 + grp + hf * 8;
            float g0 = d_G[(b * SEQ + qp) * 3 + 0];
#pragma unroll
            for (int nt = 0; nt < 2; nt++) {
                int dcol = wn * 16 + nt * 8 + 2 * t4;
                size_t ob = (size_t)(b * SEQ + qp) * 512 + h * 64 + dcol;
                *(float2*)(d_O + ob) = make_float2(o[mt][nt][2 * hf] * g0,
                                                   o[mt][nt][2 * hf + 1] * g0);
            }
        }
    __syncthreads();

    if (tid < 64) {
        float v = 0.f;
        for (int q = 0; q < 64; q++)
            v += ps[q * CS + 2 * tid] + ps[q * CS + 2 * tid + 1];
        impb[tid] = v;
    }
    __syncthreads();
    if (w == 0) {
        int j0 = lane, j1 = lane + 32;
        float v0 = (j0 <= g) ? impb[j0] + (j0 == g ? 1e9f : 0.f) : -1e30f;
        float v1 = (j1 <= g) ? impb[j1] + (j1 == g ? 1e9f : 0.f) : -1e30f;
        int selbase = ((b * NH + h) * NS + g) * TOPK;
        for (int r = 0; r < TOPK; r++) {
            float bv; int bi;
            if (v0 >= v1) { bv = v0; bi = j0; } else { bv = v1; bi = j1; }
#pragma unroll
            for (int o2 = 16; o2; o2 >>= 1) {
                float ov = __shfl_xor_sync(0xffffffffu, bv, o2);
                int   oi = __shfl_xor_sync(0xffffffffu, bi, o2);
                if (ov > bv || (ov == bv && oi < bi)) { bv = ov; bi = oi; }
            }
            if (lane == 0) d_SEL[selbase + r] = bi;
            if (bi == j0) v0 = -3e30f;
            if (bi == j1) v1 = -3e30f;
        }
    }
}

// ---------------- fused sel+win flash attention (R7 proven version) --------
#define QP 72
#define KP 68
#define VP 72
#define PP 72
__global__ __launch_bounds__(256) void selwin_fused()
{
    extern __shared__ float sm[];
    float* qs   = sm;                 // 64*72 paired
    float* Ks   = qs + 64 * QP;       // 64*68
    float* Vs   = Ks + 64 * KP;       // 64*72
    float* ps   = Vs + 64 * VP;       // 64*72 paired
    float* redm = ps + 64 * PP;       // 64*4
    float* reds = redm + 256;         // 64*4

    int g = blockIdx.x, hh = blockIdx.y, b = blockIdx.z;
    int tid = threadIdx.x, lane = tid & 31, w = tid >> 5;
    int grp = lane >> 2, t4 = lane & 3;
    int wm = w & 1, wn = w >> 1;
    int qbase = g * 64;

#pragma unroll
    for (int ii = 0; ii < 2; ii++) {
        int i = tid + ii * 256;
        int r = i >> 3, g8 = (i & 7) * 8;
        const float* src = d_Q + (size_t)(b * SEQ + qbase + r) * 512 + hh * 64 + g8;
        float4 lo = *(const float4*)src;
        float4 hi = *(const float4*)(src + 4);
        float2* dst = (float2*)(&qs[r * QP + g8]);
        dst[0] = make_float2(ftf(lo.x), ftf(hi.x));
        dst[1] = make_float2(ftf(lo.y), ftf(hi.y));
        dst[2] = make_float2(ftf(lo.z), ftf(hi.z));
        dst[3] = make_float2(ftf(lo.w), ftf(hi.w));
    }

    int selbase = ((b * NH + hh) * NS + g) * TOPK;
    int kblist[25];
    int nsel = 0;
#pragma unroll
    for (int it = 0; it < TOPK; it++) {
        int kb = d_SEL[selbase + it];
        if (kb <= g) kblist[nsel++] = kb;
    }
    int ntot = nsel;
    {
        int st = (g > 8) ? g - 8 : 0;
        for (int kb = st; kb <= g; kb++) kblist[ntot++] = kb;
    }

    float gv1[2][2], gv2[2][2];
#pragma unroll
    for (int mt = 0; mt < 2; mt++)
#pragma unroll
        for (int hf = 0; hf < 2; hf++) {
            int qp = qbase + wm * 32 + mt * 16 + grp + hf * 8;
            gv1[mt][hf] = d_G[(b * SEQ + qp) * 3 + 1];
            gv2[mt][hf] = d_G[(b * SEQ + qp) * 3 + 2];
        }

    float out_acc[2][2][4], o[2][2][4];
#pragma unroll
    for (int mt = 0; mt < 2; mt++)
#pragma unroll
        for (int nt = 0; nt < 2; nt++)
#pragma unroll
            for (int r = 0; r < 4; r++) { out_acc[mt][nt][r] = 0.f; o[mt][nt][r] = 0.f; }
    float mst[2][2], lst[2][2];
#pragma unroll
    for (int mt = 0; mt < 2; mt++)
#pragma unroll
        for (int hf = 0; hf < 2; hf++) { mst[mt][hf] = -1e30f; lst[mt][hf] = 0.f; }

    float4 kreg[4], vreg[4];
    int pr = tid >> 4, pd4 = (tid & 15) * 4;
    {
        size_t kbase = (size_t)(b * SEQ + kblist[0] * 64) * 512 + hh * 64;
#pragma unroll
        for (int j = 0; j < 4; j++) {
            kreg[j] = *(const float4*)(d_K + kbase + (size_t)(pr + j * 16) * 512 + pd4);
            vreg[j] = *(const float4*)(d_V + kbase + (size_t)(pr + j * 16) * 512 + pd4);
        }
#pragma unroll
        for (int j = 0; j < 4; j++) {
            int r = pr + j * 16;
            *(float4*)(&Ks[r * KP + pd4]) = ftf4(kreg[j]);
            *(float4*)(&Vs[r * VP + pd4]) = ftf4(vreg[j]);
        }
        int nb = (ntot > 1) ? 1 : 0;
        size_t kbase1 = (size_t)(b * SEQ + kblist[nb] * 64) * 512 + hh * 64;
#pragma unroll
        for (int j = 0; j < 4; j++) {
            kreg[j] = *(const float4*)(d_K + kbase1 + (size_t)(pr + j * 16) * 512 + pd4);
            vreg[j] = *(const float4*)(d_V + kbase1 + (size_t)(pr + j * 16) * 512 + pd4);
        }
    }
    __syncthreads();

    int posA = ((t4 & 1) << 2) + (t4 >> 1);

    for (int t = 0; t < ntot; t++) {
        if (t == nsel) {
#pragma unroll
            for (int mt = 0; mt < 2; mt++)
#pragma unroll
                for (int hf = 0; hf < 2; hf++) {
                    float inv = gv1[mt][hf] / lst[mt][hf];
#pragma unroll
                    for (int nt = 0; nt < 2; nt++) {
                        out_acc[mt][nt][2 * hf]     += o[mt][nt][2 * hf]     * inv;
                        out_acc[mt][nt][2 * hf + 1] += o[mt][nt][2 * hf + 1] * inv;
                        o[mt][nt][2 * hf] = 0.f; o[mt][nt][2 * hf + 1] = 0.f;
                    }
                    mst[mt][hf] = -1e30f; lst[mt][hf] = 0.f;
                }
        }
        int kb = kblist[t];
        bool winph = (t >= nsel);
        bool more = (t + 1 < ntot);
        int nidx = (t + 2 < ntot) ? t + 2 : ntot - 1;
        size_t nbase = (size_t)(b * SEQ + kblist[nidx] * 64) * 512 + hh * 64;

        float s[2][2][4];
#pragma unroll
        for (int mt = 0; mt < 2; mt++)
#pragma unroll
            for (int nt = 0; nt < 2; nt++)
#pragma unroll
                for (int r = 0; r < 4; r++) s[mt][nt][r] = 0.f;
#pragma unroll
        for (int ks = 0; ks < 8; ks++) {
            int kk = ks * 8;
            uint32_t af[2][4], bf[2][2];
#pragma unroll
            for (int mt = 0; mt < 2; mt++) {
                int row = wm * 32 + mt * 16 + grp;
                float2 a0 = *(float2*)(&qs[row * QP + kk + 2 * t4]);
                float2 a1 = *(float2*)(&qs[(row + 8) * QP + kk + 2 * t4]);
                af[mt][0] = U(a0.x); af[mt][2] = U(a0.y);
                af[mt][1] = U(a1.x); af[mt][3] = U(a1.y);
            }
#pragma unroll
            for (int nt = 0; nt < 2; nt++) {
                int key = wn * 16 + nt * 8 + grp;
                bf[nt][0] = U(Ks[key * KP + kk + t4]);
                bf[nt][1] = U(Ks[key * KP + kk + t4 + 4]);
            }
#pragma unroll
            for (int mt = 0; mt < 2; mt++)
#pragma unroll
                for (int nt = 0; nt < 2; nt++)
                    mma_tf32(s[mt][nt], af[mt], bf[nt]);
        }

#pragma unroll
        for (int mt = 0; mt < 2; mt++)
#pragma unroll
            for (int nt = 0; nt < 2; nt++)
#pragma unroll
                for (int r = 0; r < 4; r++) {
                    int qp = qbase + wm * 32 + mt * 16 + grp + (r >> 1) * 8;
                    int kp = kb * 64 + wn * 16 + nt * 8 + 2 * t4 + (r & 1);
                    bool valid = (kp <= qp) && (!winph || (kp + 512 > qp));
                    s[mt][nt][r] = valid ? s[mt][nt][r] * 0.125f : -1e30f;
                }

#pragma unroll
        for (int mt = 0; mt < 2; mt++)
#pragma unroll
            for (int hf = 0; hf < 2; hf++) {
                float rm = fmaxf(fmaxf(s[mt][0][2 * hf], s[mt][0][2 * hf + 1]),
                                 fmaxf(s[mt][1][2 * hf], s[mt][1][2 * hf + 1]));
                rm = fmaxf(rm, __shfl_xor_sync(0xffffffffu, rm, 1));
                rm = fmaxf(rm, __shfl_xor_sync(0xffffffffu, rm, 2));
                if (t4 == 0)
                    redm[(wm * 32 + mt * 16 + grp + hf * 8) * 4 + wn] = rm;
            }
        __syncthreads();

        if (more) {
#pragma unroll
            for (int j = 0; j < 4; j++)
                *(float4*)(&Ks[(pr + j * 16) * KP + pd4]) = ftf4(kreg[j]);
#pragma unroll
            for (int j = 0; j < 4; j++)
                kreg[j] = *(const float4*)(d_K + nbase + (size_t)(pr + j * 16) * 512 + pd4);
        }

        float corr[2][2], mnew[2][2];
#pragma unroll
        for (int mt = 0; mt < 2; mt++)
#pragma unroll
            for (int hf = 0; hf < 2; hf++) {
                int row = wm * 32 + mt * 16 + grp + hf * 8;
                float4 rmv = *(float4*)(&redm[row * 4]);
                float gmax = fmaxf(fmaxf(rmv.x, rmv.y), fmaxf(rmv.z, rmv.w));
                float mn = fmaxf(mst[mt][hf], gmax);
                mnew[mt][hf] = mn;
                corr[mt][hf] = __expf(mst[mt][hf] - mn);
            }

#pragma unroll
        for (int mt = 0; mt < 2; mt++)
#pragma unroll
            for (int hf = 0; hf < 2; hf++) {
                int rowl = wm * 32 + mt * 16 + grp + hf * 8;
                float mn = mnew[mt][hf];
                float rs = 0.f;
#pragma unroll
                for (int nt = 0; nt < 2; nt++) {
                    float p0 = __expf(s[mt][nt][2 * hf]     - mn);
                    float p1 = __expf(s[mt][nt][2 * hf + 1] - mn);
                    rs += p0 + p1;
                    int gb = wn * 16 + nt * 8;
                    ps[rowl * PP + gb + posA]     = ftf(p0);
                    ps[rowl * PP + gb + posA + 2] = ftf(p1);
                }
                rs += __shfl_xor_sync(0xffffffffu, rs, 1);
                rs += __shfl_xor_sync(0xffffffffu, rs, 2);
                if (t4 == 0) reds[rowl * 4 + wn] = rs;
            }
        __syncthreads();

#pragma unroll
        for (int mt = 0; mt < 2; mt++)
#pragma unroll
            for (int hf = 0; hf < 2; hf++) {
                int row = wm * 32 + mt * 16 + grp + hf * 8;
                float4 rsv = *(float4*)(&reds[row * 4]);
                float ls = rsv.x + rsv.y + rsv.z + rsv.w;
                float cr = corr[mt][hf];
                lst[mt][hf] = lst[mt][hf] * cr + ls;
                mst[mt][hf] = mnew[mt][hf];
#pragma unroll
                for (int nt = 0; nt < 2; nt++) {
                    o[mt][nt][2 * hf]     *= cr;
                    o[mt][nt][2 * hf + 1] *= cr;
                }
            }

#pragma unroll
        for (int ks = 0; ks < 8; ks++) {
            int kk = ks * 8;
            uint32_t af[2][4], bf[2][2];
#pragma unroll
            for (int mt = 0; mt < 2; mt++) {
                int row = wm * 32 + mt * 16 + grp;
                float2 p0 = *(float2*)(&ps[row * PP + kk + 2 * t4]);
                float2 p1 = *(float2*)(&ps[(row + 8) * PP + kk + 2 * t4]);
                af[mt][0] = U(p0.x); af[mt][2] = U(p0.y);
                af[mt][1] = U(p1.x); af[mt][3] = U(p1.y);
            }
#pragma unroll
            for (int nt = 0; nt < 2; nt++) {
                int dcol = wn * 16 + nt * 8 + grp;
                bf[nt][0] = U(Vs[(kk + t4) * VP + dcol]);
                bf[nt][1] = U(Vs[(kk + t4 + 4) * VP + dcol]);
            }
#pragma unroll
            for (int mt = 0; mt < 2; mt++)
#pragma unroll
                for (int nt = 0; nt < 2; nt++)
                    mma_tf32(o[mt][nt], af[mt], bf[nt]);
        }
        __syncthreads();

        if (more) {
#pragma unroll
            for (int j = 0; j < 4; j++)
                *(float4*)(&Vs[(pr + j * 16) * VP + pd4]) = ftf4(vreg[j]);
#pragma unroll
            for (int j = 0; j < 4; j++)
                vreg[j] = *(const float4*)(d_V + nbase + (size_t)(pr + j * 16) * 512 + pd4);
        }
    }

#pragma unroll
    for (int mt = 0; mt < 2; mt++)
#pragma unroll
        for (int hf = 0; hf < 2; hf++) {
            int qp = qbase + wm * 32 + mt * 16 + grp + hf * 8;
            float inv = gv2[mt][hf] / lst[mt][hf];
#pragma unroll
            for (int nt = 0; nt < 2; nt++) {
                int dcol = wn * 16 + nt * 8 + 2 * t4;
                size_t ob = (size_t)(b * SEQ + qp) * 512 + hh * 64 + dcol;
                float2 cur = *(float2*)(d_O + ob);
                cur.x += out_acc[mt][nt][2 * hf]     + o[mt][nt][2 * hf]     * inv;
                cur.y += out_acc[mt][nt][2 * hf + 1] + o[mt][nt][2 * hf + 1] * inv;
                *(float2*)(d_O + ob) = cur;
            }
        }
}

// ---------------------------------------------------------------------------
extern "C" void kernel_launch(void* const* d_in, const int* in_sizes, int n_in,
                              void* d_out, int out_size)
{
    const float* x  = (const float*)d_in[0];
    const float* Wq = (const float*)d_in[1];
    const float* Wk = (const float*)d_in[2];
    const float* Wv = (const float*)d_in[3];
    const float* Wo = (const float*)d_in[4];
    const float* Wg = (const float*)d_in[5];
    float* y = (float*)d_out;

    cudaFuncSetAttribute(gemm512_tc,
                         cudaFuncAttributeMaxDynamicSharedMemorySize, 71680);
    cudaFuncSetAttribute(cmp_attn_mma,
                         cudaFuncAttributeMaxDynamicSharedMemorySize, 90368);
    cudaFuncSetAttribute(selwin_fused,
                         cudaFuncAttributeMaxDynamicSharedMemorySize, 74752);

    gemm512_tc<<<dim3(4, 64, 3), 256, 71680>>>(x, Wq, Wk, Wv, nullptr, 0);
    gate_kernel<<<NROWS / 8, 256>>>(x, Wg);
    compress_kernel<<<(BATCH * NH * NC * HD) / 256, 256>>>();
    cmp_attn_mma<<<dim3(64, 8, 2), 256, 90368>>>();
    selwin_fused<<<dim3(64, 8, 2), 256, 74752>>>();
    gemm512_tc<<<dim3(4, 64, 1), 256, 71680>>>(nullptr, Wo, nullptr, nullptr, y, 3);
}